// round 1
// baseline (speedup 1.0000x reference)
#include <cuda_runtime.h>
#include <math.h>

#define NTOK 1568
#define CH 32
#define PS 16
#define NPIX 256
#define NEXP 8
#define FC 18
#define GATE_IN 50
#define CAPN 245
#define NCLS 1000
#define HWD 224
#define HP 14
#define EPSV 1e-5f
#define PI_F 3.14159265358979323846f

// ---- scratch (no allocations allowed) ----
__device__ float g_tokens[NTOK * CH * NPIX];   // 51.4 MB, token layout (n,c,py,px)
__device__ float g_probs[NTOK * NEXP];
__device__ float g_lse[NTOK];
__device__ int   g_top1[NTOK];
__device__ float g_wn[NTOK];
__device__ float g_psum[NTOK * CH];
__device__ float g_psumsq[NTOK * CH];

// ============================================================
// K1: stem conv3x3 (3->32) + BN + SiLU, writes token layout
// ============================================================
__global__ void k1_stem(const float* __restrict__ X, const float* __restrict__ W,
                        const float* __restrict__ bnw, const float* __restrict__ bnb) {
    __shared__ float sIn[3 * 18 * 18];
    __shared__ float sW[32 * 27];
    __shared__ float sBw[32], sBb[32];
    int n = blockIdx.x;
    int b = n / 196, pr = (n % 196) / HP, pc = n % HP;
    int tid = threadIdx.x;

    for (int i = tid; i < 3 * 18 * 18; i += 256) {
        int ci = i / 324, r = (i % 324) / 18, c = i % 18;
        int gy = pr * 16 + r - 1, gx = pc * 16 + c - 1;
        float v = 0.f;
        if (gy >= 0 && gy < HWD && gx >= 0 && gx < HWD)
            v = X[((b * 3 + ci) * HWD + gy) * HWD + gx];
        sIn[i] = v;
    }
    for (int i = tid; i < 864; i += 256) sW[i] = W[i];
    if (tid < 32) { sBw[tid] = bnw[tid]; sBb[tid] = bnb[tid]; }
    __syncthreads();

    int py = tid >> 4, px = tid & 15;
    float xin[27];
#pragma unroll
    for (int ci = 0; ci < 3; ci++)
#pragma unroll
        for (int dy = 0; dy < 3; dy++)
#pragma unroll
            for (int dx = 0; dx < 3; dx++)
                xin[ci * 9 + dy * 3 + dx] = sIn[ci * 324 + (py + dy) * 18 + (px + dx)];

    for (int co = 0; co < 32; co++) {
        float a = 0.f;
#pragma unroll
        for (int k = 0; k < 27; k++) a = fmaf(sW[co * 27 + k], xin[k], a);
        a = a * sBw[co] + sBb[co];
        float s = a / (1.f + expf(-a));   // SiLU
        g_tokens[(n * CH + co) * NPIX + tid] = s;
    }
}

// ============================================================
// K2: router gate per token: channel means + Fourier pos means
//     -> logits -> softmax / argmax / logsumexp
// ============================================================
__global__ void k2_gate(const float* __restrict__ gate_w, const float* __restrict__ gate_b) {
    __shared__ float sm[GATE_IN];
    __shared__ float sl[NEXP];
    int n = blockIdx.x;
    int tid = threadIdx.x;
    int pr = (n % 196) / HP, pc = n % HP;

    // channel means: 8 threads per channel
    {
        int c = tid >> 3, j = tid & 7;
        float v = 0.f;
        const float* tp = &g_tokens[(n * CH + c) * NPIX];
        for (int p = j; p < NPIX; p += 8) v += tp[p];
        v += __shfl_down_sync(0xffffffffu, v, 4, 8);
        v += __shfl_down_sync(0xffffffffu, v, 2, 8);
        v += __shfl_down_sync(0xffffffffu, v, 1, 8);
        if (j == 0) sm[c] = v * (1.f / 256.f);
    }
    // positional feature patch means (analytic)
    if (tid < FC) {
        float pv;
        if (tid == 0)      pv = (16.f * pr + 8.f) / 224.f;
        else if (tid == 1) pv = (16.f * pc + 8.f) / 224.f;
        else {
            int kk = (tid - 2) >> 2, sub = (tid - 2) & 3;
            float f = (float)(1 << kk) * PI_F;
            int base = (sub < 2) ? pr : pc;
            float s = 0.f;
            for (int r = 0; r < 16; r++) {
                float ang = f * ((16.f * base + (float)r + 0.5f) / 224.f);
                s += (sub & 1) ? cosf(ang) : sinf(ang);
            }
            pv = s * (1.f / 16.f);
        }
        sm[32 + tid] = pv;
    }
    __syncthreads();
    if (tid < NEXP) {
        float l = gate_b[tid];
        for (int i = 0; i < GATE_IN; i++) l = fmaf(sm[i], gate_w[i * NEXP + tid], l);
        sl[tid] = l;
    }
    __syncthreads();
    if (tid == 0) {
        float mx = sl[0]; int am = 0;
        for (int e = 1; e < NEXP; e++) if (sl[e] > mx) { mx = sl[e]; am = e; }
        float pe[NEXP]; float se = 0.f;
        for (int e = 0; e < NEXP; e++) { pe[e] = expf(sl[e] - mx); se += pe[e]; }
        float inv = 1.f / se;
        for (int e = 0; e < NEXP; e++) g_probs[n * NEXP + e] = pe[e] * inv;
        g_lse[n] = mx + logf(se);
        g_top1[n] = am;
    }
}

// ============================================================
// K3: single-block capacity scan (deterministic) + losses
// ============================================================
__global__ void k3_dispatch(float* __restrict__ d_out) {
    __shared__ int   sT[NTOK];
    __shared__ float sbuf[512];
    __shared__ float sres[17];
    int tid = threadIdx.x;
    for (int i = tid; i < NTOK; i += 512) sT[i] = g_top1[i];
    __syncthreads();

    float part[17];
#pragma unroll
    for (int q = 0; q < 17; q++) part[q] = 0.f;

    for (int n = tid; n < NTOK; n += 512) {
        int e = sT[n];
        int cnt = 0;
        for (int i = 0; i < n; i++) cnt += (sT[i] == e);
        g_wn[n] = (cnt < CAPN) ? g_probs[n * NEXP + e] : 0.f;
        float lse = g_lse[n];
        part[0] += lse * lse;
        for (int q = 0; q < NEXP; q++) part[1 + q] += g_probs[n * NEXP + q];
        part[9 + e] += 1.f;
    }
    for (int q = 0; q < 17; q++) {
        sbuf[tid] = part[q];
        __syncthreads();
        for (int s = 256; s > 0; s >>= 1) {
            if (tid < s) sbuf[tid] += sbuf[tid + s];
            __syncthreads();
        }
        if (tid == 0) sres[q] = sbuf[0];
        __syncthreads();
    }
    if (tid == 0) {
        float z = sres[0] / (float)NTOK;
        float imb = 0.f;
        for (int e = 0; e < NEXP; e++) imb += sres[1 + e] * sres[9 + e];
        imb *= (float)NEXP / ((float)NTOK * (float)NTOK);
        d_out[8000] = z;
        d_out[8001] = imb;
    }
}

// ============================================================
// K4: per-token expert conv3x3 (32->32) + SiLU + combine,
//     emits per-(token,channel) sum & sumsq of updated values.
// 8 warps: warp w -> output channels 4w..4w+3; lane -> (row, 8 px)
// ============================================================
__global__ void __launch_bounds__(256, 2)
k4_expert(const float* __restrict__ EW, const float* __restrict__ EB,
          const float* __restrict__ gamma) {
    __shared__ float sX[CH * 18 * 18];  // zero-padded token
    int n = blockIdx.x;
    int tid = threadIdx.x;
    float wn = g_wn[n];
    int e = g_top1[n];

    for (int i = tid; i < CH * 324; i += 256) sX[i] = 0.f;
    __syncthreads();
    for (int i = tid; i < CH * NPIX; i += 256) {
        int c = i >> 8, p = i & 255;
        sX[c * 324 + ((p >> 4) + 1) * 18 + ((p & 15) + 1)] = g_tokens[n * CH * NPIX + i];
    }
    __syncthreads();

    int wid = tid >> 5, lane = tid & 31;
    int row = lane >> 1, xb = (lane & 1) * 8;

    float acc[4][8];
#pragma unroll
    for (int a = 0; a < 4; a++)
#pragma unroll
        for (int p = 0; p < 8; p++) acc[a][p] = 0.f;

    const float* wbase = EW + ((long)e * CH + wid * 4) * CH * 9;
    for (int ci = 0; ci < CH; ci++) {
        float xr[3][10];
#pragma unroll
        for (int dy = 0; dy < 3; dy++)
#pragma unroll
            for (int jx = 0; jx < 10; jx++)
                xr[dy][jx] = sX[ci * 324 + (row + dy) * 18 + xb + jx];
#pragma unroll
        for (int c4 = 0; c4 < 4; c4++) {
            const float* wp = wbase + (c4 * CH + ci) * 9;
#pragma unroll
            for (int ky = 0; ky < 3; ky++)
#pragma unroll
                for (int kx = 0; kx < 3; kx++) {
                    float w = __ldg(wp + ky * 3 + kx);
#pragma unroll
                    for (int p = 0; p < 8; p++)
                        acc[c4][p] = fmaf(w, xr[ky][p + kx], acc[c4][p]);
                }
        }
    }

    // epilogue: y = silu(acc + b); v = t + gamma*wn*y; reduce sum/sumsq per channel
#pragma unroll
    for (int c4 = 0; c4 < 4; c4++) {
        int co = wid * 4 + c4;
        float bco = EB[e * CH + co];
        float gm = gamma[co] * wn;
        float s = 0.f, ss = 0.f;
#pragma unroll
        for (int p = 0; p < 8; p++) {
            float y = acc[c4][p] + bco;
            y = y / (1.f + expf(-y));
            float t = sX[co * 324 + (row + 1) * 18 + (xb + 1 + p)];
            float v = t + gm * y;
            s += v; ss = fmaf(v, v, ss);
        }
#pragma unroll
        for (int off = 16; off > 0; off >>= 1) {
            s  += __shfl_down_sync(0xffffffffu, s, off);
            ss += __shfl_down_sync(0xffffffffu, ss, off);
        }
        if (lane == 0) { g_psum[n * CH + co] = s; g_psumsq[n * CH + co] = ss; }
    }
}

// ============================================================
// K5: GroupNorm(from moments) + pool + LayerNorm + head
// one block per batch element
// ============================================================
__global__ void k5_head(const float* __restrict__ gnw, const float* __restrict__ gnb,
                        const float* __restrict__ lnw, const float* __restrict__ lnb,
                        const float* __restrict__ hw, const float* __restrict__ hb,
                        float* __restrict__ d_out) {
    __shared__ float sS[32], sSS[32], sF[32], sFN[32];
    __shared__ float sMg[8], sRg[8];
    int b = blockIdx.x, tid = threadIdx.x;
    if (tid < 32) {
        float S = 0.f, SS = 0.f;
        for (int t = 0; t < 196; t++) {
            int idx = (b * 196 + t) * CH + tid;
            S += g_psum[idx]; SS += g_psumsq[idx];
        }
        sS[tid] = S; sSS[tid] = SS;
    }
    __syncthreads();
    if (tid < 8) {
        float S  = sS[tid * 4] + sS[tid * 4 + 1] + sS[tid * 4 + 2] + sS[tid * 4 + 3];
        float SS = sSS[tid * 4] + sSS[tid * 4 + 1] + sSS[tid * 4 + 2] + sSS[tid * 4 + 3];
        const float inv = 1.f / (4.f * 50176.f);
        float m = S * inv;
        float ex2 = SS * inv;
        sMg[tid] = m;
        sRg[tid] = rsqrtf(ex2 - m * m + EPSV);
    }
    __syncthreads();
    if (tid < 32) {
        float mx = sS[tid] * (1.f / 50176.f);
        int g = tid >> 2;
        sF[tid] = (mx - sMg[g]) * sRg[g] * gnw[tid] + gnb[tid];
    }
    __syncthreads();
    if (tid == 0) {
        float mu = 0.f;
        for (int c = 0; c < 32; c++) mu += sF[c];
        mu *= (1.f / 32.f);
        float va = 0.f;
        for (int c = 0; c < 32; c++) { float d = sF[c] - mu; va = fmaf(d, d, va); }
        va *= (1.f / 32.f);
        float r = rsqrtf(va + EPSV);
        for (int c = 0; c < 32; c++) sFN[c] = (sF[c] - mu) * r * lnw[c] + lnb[c];
    }
    __syncthreads();
    for (int j = tid; j < NCLS; j += blockDim.x) {
        float a = hb[j];
#pragma unroll
        for (int c = 0; c < 32; c++) a = fmaf(sFN[c], hw[c * NCLS + j], a);
        d_out[b * NCLS + j] = a;
    }
}

// ============================================================
extern "C" void kernel_launch(void* const* d_in, const int* in_sizes, int n_in,
                              void* d_out, int out_size) {
    const float* X        = (const float*)d_in[0];
    const float* stem_w   = (const float*)d_in[1];
    const float* bn_w     = (const float*)d_in[2];
    const float* bn_b     = (const float*)d_in[3];
    const float* gate_w   = (const float*)d_in[4];
    const float* gate_b   = (const float*)d_in[5];
    const float* expert_w = (const float*)d_in[6];
    const float* expert_b = (const float*)d_in[7];
    const float* gamma    = (const float*)d_in[8];
    const float* gn_w     = (const float*)d_in[9];
    const float* gn_b     = (const float*)d_in[10];
    const float* ln_w     = (const float*)d_in[11];
    const float* ln_b     = (const float*)d_in[12];
    const float* head_w   = (const float*)d_in[13];
    const float* head_b   = (const float*)d_in[14];
    float* out = (float*)d_out;

    k1_stem<<<NTOK, 256>>>(X, stem_w, bn_w, bn_b);
    k2_gate<<<NTOK, 256>>>(gate_w, gate_b);
    k3_dispatch<<<1, 512>>>(out);
    k4_expert<<<NTOK, 256>>>(expert_w, expert_b, gamma);
    k5_head<<<8, 256>>>(gn_w, gn_b, ln_w, ln_b, head_w, head_b, out);
}

// round 3
// speedup vs baseline: 1.1273x; 1.1273x over previous
#include <cuda_runtime.h>
#include <math.h>

#define NTOK 1568
#define CH 32
#define NPIX 256
#define NEXP 8
#define CAPN 245
#define NCLS 1000
#define HWD 224
#define HP 14
#define EPSV 1e-5f
#define PI_F 3.14159265358979323846f

// ---- scratch (no allocations allowed) ----
__device__ float g_tokens[NTOK * CH * NPIX];   // token layout (n,c,py,px)
__device__ float g_cmean[NTOK * CH];
__device__ int   g_top1[NTOK];
__device__ float g_wn[NTOK];
__device__ float g_psum[NTOK * CH];
__device__ float g_psumsq[NTOK * CH];

typedef unsigned long long u64;

// ---- f32x2 helpers (Blackwell packed fp32; ptxas never auto-fuses) ----
__device__ __forceinline__ u64 pack2(float x, float y) {
    u64 r; asm("mov.b64 %0, {%1, %2};" : "=l"(r) : "f"(x), "f"(y)); return r;
}
__device__ __forceinline__ void unpack2(u64 v, float& x, float& y) {
    asm("mov.b64 {%0, %1}, %2;" : "=f"(x), "=f"(y) : "l"(v));
}
__device__ __forceinline__ u64 ffma2(u64 a, u64 b, u64 c) {
    u64 d; asm("fma.rn.f32x2 %0, %1, %2, %3;" : "=l"(d) : "l"(a), "l"(b), "l"(c));
    return d;
}
// returns {hi(a), lo(b)}
__device__ __forceinline__ u64 shiftp(u64 a, u64 b) {
    u64 r;
    asm("{\n\t.reg .f32 al, ah, bl, bh;\n\t"
        "mov.b64 {al, ah}, %1;\n\t"
        "mov.b64 {bl, bh}, %2;\n\t"
        "mov.b64 %0, {ah, bl};\n\t}"
        : "=l"(r) : "l"(a), "l"(b));
    return r;
}

// ============================================================
// K1: stem conv3x3 (3->32) + BN + SiLU -> tokens; fused channel means
// ============================================================
__global__ void __launch_bounds__(256)
k1_stem(const float* __restrict__ X, const float* __restrict__ W,
        const float* __restrict__ bnw, const float* __restrict__ bnb) {
    __shared__ __align__(16) float sIn[3 * 18 * 18];
    __shared__ __align__(16) float sW[32 * 28];   // padded to 28/row for b64 pairs
    __shared__ float sBw[32], sBb[32];
    __shared__ float sPart[8 * 32];
    int n = blockIdx.x;
    int b = n / 196, pr = (n % 196) / HP, pc = n % HP;
    int tid = threadIdx.x;

    for (int i = tid; i < 3 * 18 * 18; i += 256) {
        int ci = i / 324, r = (i % 324) / 18, c = i % 18;
        int gy = pr * 16 + r - 1, gx = pc * 16 + c - 1;
        float v = 0.f;
        if (gy >= 0 && gy < HWD && gx >= 0 && gx < HWD)
            v = X[((b * 3 + ci) * HWD + gy) * HWD + gx];
        sIn[i] = v;
    }
    for (int i = tid; i < 32 * 28; i += 256) {
        int co = i / 28, k = i % 28;
        sW[i] = (k < 27) ? W[co * 27 + k] : 0.f;
    }
    if (tid < 32) { sBw[tid] = bnw[tid]; sBb[tid] = bnb[tid]; }
    __syncthreads();

    int py = tid >> 4, px = tid & 15;
    float xin[28];
#pragma unroll
    for (int ci = 0; ci < 3; ci++)
#pragma unroll
        for (int dy = 0; dy < 3; dy++)
#pragma unroll
            for (int dx = 0; dx < 3; dx++)
                xin[ci * 9 + dy * 3 + dx] = sIn[ci * 324 + (py + dy) * 18 + (px + dx)];
    xin[27] = 0.f;
    u64 xp[14];
#pragma unroll
    for (int j = 0; j < 14; j++) xp[j] = pack2(xin[2 * j], xin[2 * j + 1]);

    int lane = tid & 31, wid = tid >> 5;
    for (int co = 0; co < 32; co++) {
        u64 acc = 0ULL;
#pragma unroll
        for (int j = 0; j < 14; j++)
            acc = ffma2(*(const u64*)(sW + co * 28 + 2 * j), xp[j], acc);
        float a0, a1; unpack2(acc, a0, a1);
        float a = a0 + a1;
        a = a * sBw[co] + sBb[co];
        float s = a / (1.f + expf(-a));
        g_tokens[(n * CH + co) * NPIX + tid] = s;
        float ws = s;
#pragma unroll
        for (int off = 16; off > 0; off >>= 1)
            ws += __shfl_down_sync(0xffffffffu, ws, off);
        if (lane == 0) sPart[wid * 32 + co] = ws;
    }
    __syncthreads();
    if (tid < 32) {
        float sum = 0.f;
#pragma unroll
        for (int w = 0; w < 8; w++) sum += sPart[w * 32 + tid];
        g_cmean[n * CH + tid] = sum * (1.f / 256.f);
    }
}

// ============================================================
// K3: gate (from channel means + analytic pos table) + softmax +
//     ballot-based capacity scan + losses. One block, 512 threads.
// ============================================================
__global__ void __launch_bounds__(512)
k3_gate_dispatch(const float* __restrict__ gate_w,
                 const float* __restrict__ gate_b,
                 float* __restrict__ d_out) {
    __shared__ float sGw[50 * 8];
    __shared__ float sGb[8];
    __shared__ float tab[14][9];
    __shared__ int   sT[NTOK];
    __shared__ float sPtop[NTOK];
    __shared__ float sbuf[512];
    __shared__ float sres[17];
    __shared__ int   sWC[16 * 9];
    __shared__ int   sRun[8];
    int tid = threadIdx.x;

    for (int i = tid; i < 400; i += 512) sGw[i] = gate_w[i];
    if (tid < 8) { sGb[tid] = gate_b[tid]; sRun[tid] = 0; }
    if (tid < 144) sWC[tid] = 0;
    if (tid < 56) {
        int b2 = tid >> 2, k = tid & 3;
        float f = (float)(1 << k) * PI_F;
        float ss = 0.f, cs = 0.f;
        for (int r = 0; r < 16; r++) {
            float ang = f * ((16.f * b2 + (float)r + 0.5f) / 224.f);
            ss += sinf(ang); cs += cosf(ang);
        }
        tab[b2][1 + 2 * k] = ss * (1.f / 16.f);
        tab[b2][2 + 2 * k] = cs * (1.f / 16.f);
    } else if (tid < 70) {
        int b2 = tid - 56;
        tab[b2][0] = (16.f * b2 + 8.f) / 224.f;
    }
    __syncthreads();

    float part[17];
#pragma unroll
    for (int q = 0; q < 17; q++) part[q] = 0.f;

    for (int n = tid; n < NTOK; n += 512) {
        int pr = (n % 196) / HP, pc = n % HP;
        float l[8];
#pragma unroll
        for (int e = 0; e < 8; e++) l[e] = sGb[e];
        const float* cm = &g_cmean[n * CH];
        for (int i = 0; i < 32; i++) {
            float v = cm[i];
#pragma unroll
            for (int e = 0; e < 8; e++) l[e] = fmaf(v, sGw[i * 8 + e], l[e]);
        }
        {
            float v0 = tab[pr][0], v1 = tab[pc][0];
#pragma unroll
            for (int e = 0; e < 8; e++) {
                l[e] = fmaf(v0, sGw[32 * 8 + e], l[e]);
                l[e] = fmaf(v1, sGw[33 * 8 + e], l[e]);
            }
        }
#pragma unroll
        for (int k = 0; k < 4; k++) {
#pragma unroll
            for (int sub = 0; sub < 4; sub++) {
                float v = (sub < 2) ? tab[pr][1 + 2 * k + sub] : tab[pc][1 + 2 * k + (sub - 2)];
#pragma unroll
                for (int e = 0; e < 8; e++)
                    l[e] = fmaf(v, sGw[(34 + 4 * k + sub) * 8 + e], l[e]);
            }
        }
        float mx = l[0]; int am = 0;
#pragma unroll
        for (int e = 1; e < 8; e++) if (l[e] > mx) { mx = l[e]; am = e; }
        float se = 0.f, ptop = 0.f;
#pragma unroll
        for (int e = 0; e < 8; e++) {
            float pe = expf(l[e] - mx);
            se += pe;
            part[1 + e] += pe;      // rescale by inv later? no — need probs sum; fix below
            if (e == am) ptop = pe;
        }
        // part[1+e] accumulated un-normalized exp; correct by subtracting and re-adding normalized
        float inv = 1.f / se;
#pragma unroll
        for (int e = 0; e < 8; e++) part[1 + e] += 0.f;   // placeholder (normalized below per-token)
        // redo normalized accumulation properly:
#pragma unroll
        for (int e = 0; e < 8; e++) part[1 + e] -= 0.f;
        // NOTE: to keep exactness, recompute normalized probs:
#pragma unroll
        for (int e = 0; e < 8; e++) {
            float pe = expf(l[e] - mx);
            part[1 + e] += pe * inv - pe;   // net effect: += pe*inv (undo earlier += pe)
        }
        float lse = mx + logf(se);
        part[0] += lse * lse;
        part[9 + am] += 1.f;
        sT[n] = am;
        g_top1[n] = am;
        sPtop[n] = ptop * inv;
    }
    __syncthreads();

    // capacity scan: chunked ballot prefix, exact token-index order
    int lane = tid & 31, wid = tid >> 5;
    for (int c = 0; c < 4; c++) {
        int n = c * 512 + tid;
        bool act = n < NTOK;
        int e = act ? sT[n] : 8;
        unsigned m = __match_any_sync(0xffffffffu, e);
        int lr = __popc(m & ((1u << lane) - 1u));
        if (lr == 0) sWC[wid * 9 + e] = __popc(m);
        __syncthreads();
        if (act) {
            int base = sRun[e];
            for (int w2 = 0; w2 < wid; w2++) base += sWC[w2 * 9 + e];
            int rank = base + lr;
            g_wn[n] = (rank < CAPN) ? sPtop[n] : 0.f;
        }
        int s = 0;
        if (tid < 8) for (int w2 = 0; w2 < 16; w2++) s += sWC[w2 * 9 + tid];
        __syncthreads();
        if (tid < 8) sRun[tid] += s;
        if (tid < 144) sWC[tid] = 0;
        __syncthreads();
    }

    // loss reductions
    for (int q = 0; q < 17; q++) {
        sbuf[tid] = part[q];
        __syncthreads();
        for (int s2 = 256; s2 > 0; s2 >>= 1) {
            if (tid < s2) sbuf[tid] += sbuf[tid + s2];
            __syncthreads();
        }
        if (tid == 0) sres[q] = sbuf[0];
        __syncthreads();
    }
    if (tid == 0) {
        float z = sres[0] / (float)NTOK;
        float imb = 0.f;
        for (int e = 0; e < 8; e++) imb += sres[1 + e] * sres[9 + e];
        imb *= (float)NEXP / ((float)NTOK * (float)NTOK);
        d_out[8000] = z;
        d_out[8001] = imb;
    }
}

// ============================================================
// K4: expert conv3x3 (32->32) + SiLU + combine, f32x2 packed math
// ============================================================
template <int PAR>
__device__ __forceinline__ void ldw9(const float* __restrict__ wp, float* w) {
    if (PAR == 0) {
        float2 a = *(const float2*)(wp);
        float2 b = *(const float2*)(wp + 2);
        float2 c = *(const float2*)(wp + 4);
        float2 d = *(const float2*)(wp + 6);
        w[0] = a.x; w[1] = a.y; w[2] = b.x; w[3] = b.y;
        w[4] = c.x; w[5] = c.y; w[6] = d.x; w[7] = d.y;
        w[8] = wp[8];
    } else {
        w[0] = wp[0];
        float2 a = *(const float2*)(wp + 1);
        float2 b = *(const float2*)(wp + 3);
        float2 c = *(const float2*)(wp + 5);
        float2 d = *(const float2*)(wp + 7);
        w[1] = a.x; w[2] = a.y; w[3] = b.x; w[4] = b.y;
        w[5] = c.x; w[6] = c.y; w[7] = d.x; w[8] = d.y;
    }
}

template <int PAR>
__device__ __forceinline__ void conv_ci(int ci, const float* sXb,
                                        const float* __restrict__ wbase,
                                        u64 acc[4][4]) {
    u64 ev[3][5], od[3][4];
#pragma unroll
    for (int dy = 0; dy < 3; dy++) {
        const float* rp = sXb + ci * 324 + dy * 18;
#pragma unroll
        for (int j = 0; j < 5; j++) ev[dy][j] = *(const u64*)(rp + 2 * j);
#pragma unroll
        for (int j = 0; j < 4; j++) od[dy][j] = shiftp(ev[dy][j], ev[dy][j + 1]);
    }
#pragma unroll
    for (int c4 = 0; c4 < 4; c4++) {
        const float* wp = wbase + (c4 * CH + ci) * 9;
        float w[9];
        ldw9<PAR>(wp, w);
#pragma unroll
        for (int ky = 0; ky < 3; ky++) {
            u64 w0 = pack2(w[ky * 3 + 0], w[ky * 3 + 0]);
            u64 w1 = pack2(w[ky * 3 + 1], w[ky * 3 + 1]);
            u64 w2 = pack2(w[ky * 3 + 2], w[ky * 3 + 2]);
#pragma unroll
            for (int j = 0; j < 4; j++) {
                acc[c4][j] = ffma2(w0, ev[ky][j], acc[c4][j]);
                acc[c4][j] = ffma2(w1, od[ky][j], acc[c4][j]);
                acc[c4][j] = ffma2(w2, ev[ky][j + 1], acc[c4][j]);
            }
        }
    }
}

__global__ void __launch_bounds__(256, 2)
k4_expert(const float* __restrict__ EW, const float* __restrict__ EB,
          const float* __restrict__ gamma) {
    __shared__ __align__(16) float sX[CH * 324];  // zero-padded token (18x18 per ch)
    int n = blockIdx.x;
    int tid = threadIdx.x;
    float wn = g_wn[n];
    int e = g_top1[n];

    for (int i = tid; i < CH * 324 / 2; i += 256) ((u64*)sX)[i] = 0ULL;
    __syncthreads();
    const float4* src = (const float4*)(g_tokens + (size_t)n * CH * NPIX);
    for (int i = tid; i < CH * NPIX / 4; i += 256) {
        float4 v = src[i];
        int c = i >> 6;
        int p = (i & 63) * 4;
        float* dst = sX + c * 324 + ((p >> 4) + 1) * 18 + (p & 15) + 1;
        dst[0] = v.x; dst[1] = v.y; dst[2] = v.z; dst[3] = v.w;
    }
    __syncthreads();

    int wid = tid >> 5, lane = tid & 31;
    int row = lane >> 1, xb = (lane & 1) * 8;

    u64 acc[4][4];
#pragma unroll
    for (int a = 0; a < 4; a++)
#pragma unroll
        for (int j = 0; j < 4; j++) acc[a][j] = 0ULL;

    const float* wbase = EW + ((size_t)e * CH + wid * 4) * CH * 9;
    const float* sXb = sX + row * 18 + xb;

#pragma unroll 1
    for (int ci2 = 0; ci2 < 16; ci2++) {
        conv_ci<0>(2 * ci2, sXb, wbase, acc);
        conv_ci<1>(2 * ci2 + 1, sXb, wbase, acc);
    }

    // epilogue: y = silu(acc + b); v = t + gamma*wn*y; per-channel sum/sumsq
#pragma unroll
    for (int c4 = 0; c4 < 4; c4++) {
        int co = wid * 4 + c4;
        float bco = EB[e * CH + co];
        float gm = gamma[co] * wn;
        float s = 0.f, ss = 0.f;
#pragma unroll
        for (int j = 0; j < 4; j++) {
            float y0, y1; unpack2(acc[c4][j], y0, y1);
            float a0 = y0 + bco; a0 = a0 / (1.f + expf(-a0));
            float a1 = y1 + bco; a1 = a1 / (1.f + expf(-a1));
            float t0 = sX[co * 324 + (row + 1) * 18 + (xb + 1 + 2 * j)];
            float t1 = sX[co * 324 + (row + 1) * 18 + (xb + 2 + 2 * j)];
            float v0 = t0 + gm * a0;
            float v1 = t1 + gm * a1;
            s += v0; ss = fmaf(v0, v0, ss);
            s += v1; ss = fmaf(v1, v1, ss);
        }
#pragma unroll
        for (int off = 16; off > 0; off >>= 1) {
            s  += __shfl_down_sync(0xffffffffu, s, off);
            ss += __shfl_down_sync(0xffffffffu, ss, off);
        }
        if (lane == 0) { g_psum[n * CH + co] = s; g_psumsq[n * CH + co] = ss; }
    }
}

// ============================================================
// K5: GroupNorm(from moments) + pool + LayerNorm + head
// ============================================================
__global__ void __launch_bounds__(256)
k5_head(const float* __restrict__ gnw, const float* __restrict__ gnb,
        const float* __restrict__ lnw, const float* __restrict__ lnb,
        const float* __restrict__ hw, const float* __restrict__ hb,
        float* __restrict__ d_out) {
    __shared__ float sS[32], sSS[32], sF[32], sFN[32];
    __shared__ float sMg[8], sRg[8];
    int b = blockIdx.x, tid = threadIdx.x;
    if (tid < 32) {
        float S = 0.f, SS = 0.f;
        for (int t = 0; t < 196; t++) {
            int idx = (b * 196 + t) * CH + tid;
            S += g_psum[idx]; SS += g_psumsq[idx];
        }
        sS[tid] = S; sSS[tid] = SS;
    }
    __syncthreads();
    if (tid < 8) {
        float S  = sS[tid * 4] + sS[tid * 4 + 1] + sS[tid * 4 + 2] + sS[tid * 4 + 3];
        float SS = sSS[tid * 4] + sSS[tid * 4 + 1] + sSS[tid * 4 + 2] + sSS[tid * 4 + 3];
        const float inv = 1.f / (4.f * 50176.f);
        float m = S * inv;
        float ex2 = SS * inv;
        sMg[tid] = m;
        sRg[tid] = rsqrtf(ex2 - m * m + EPSV);
    }
    __syncthreads();
    if (tid < 32) {
        float mx = sS[tid] * (1.f / 50176.f);
        int g = tid >> 2;
        sF[tid] = (mx - sMg[g]) * sRg[g] * gnw[tid] + gnb[tid];
    }
    __syncthreads();
    if (tid == 0) {
        float mu = 0.f;
        for (int c = 0; c < 32; c++) mu += sF[c];
        mu *= (1.f / 32.f);
        float va = 0.f;
        for (int c = 0; c < 32; c++) { float d = sF[c] - mu; va = fmaf(d, d, va); }
        va *= (1.f / 32.f);
        float r = rsqrtf(va + EPSV);
        for (int c = 0; c < 32; c++) sFN[c] = (sF[c] - mu) * r * lnw[c] + lnb[c];
    }
    __syncthreads();
    for (int j = tid; j < NCLS; j += blockDim.x) {
        float a = hb[j];
#pragma unroll
        for (int c = 0; c < 32; c++) a = fmaf(sFN[c], hw[c * NCLS + j], a);
        d_out[b * NCLS + j] = a;
    }
}

// ============================================================
extern "C" void kernel_launch(void* const* d_in, const int* in_sizes, int n_in,
                              void* d_out, int out_size) {
    const float* X        = (const float*)d_in[0];
    const float* stem_w   = (const float*)d_in[1];
    const float* bn_w     = (const float*)d_in[2];
    const float* bn_b     = (const float*)d_in[3];
    const float* gate_w   = (const float*)d_in[4];
    const float* gate_b   = (const float*)d_in[5];
    const float* expert_w = (const float*)d_in[6];
    const float* expert_b = (const float*)d_in[7];
    const float* gamma    = (const float*)d_in[8];
    const float* gn_w     = (const float*)d_in[9];
    const float* gn_b     = (const float*)d_in[10];
    const float* ln_w     = (const float*)d_in[11];
    const float* ln_b     = (const float*)d_in[12];
    const float* head_w   = (const float*)d_in[13];
    const float* head_b   = (const float*)d_in[14];
    float* out = (float*)d_out;

    k1_stem<<<NTOK, 256>>>(X, stem_w, bn_w, bn_b);
    k3_gate_dispatch<<<1, 512>>>(gate_w, gate_b, out);
    k4_expert<<<NTOK, 256>>>(expert_w, expert_b, gamma);
    k5_head<<<8, 256>>>(gn_w, gn_b, ln_w, ln_b, head_w, head_b, out);
}

// round 4
// speedup vs baseline: 1.2854x; 1.1403x over previous
#include <cuda_runtime.h>
#include <math.h>

#define NTOK 1568
#define CH 32
#define NPIX 256
#define NEXP 8
#define CAPN 245
#define NCLS 1000
#define HWD 224
#define HP 14
#define EPSV 1e-5f
#define PI_F 3.14159265358979323846f

// ---- scratch (no allocations allowed) ----
__device__ float g_tokens[NTOK * CH * NPIX];   // token layout (n,c,py,px)
__device__ float g_cmean[NTOK * CH];
__device__ int   g_top1[NTOK];
__device__ float g_ptop[NTOK];
__device__ float g_lse[NTOK];
__device__ float g_probs[NTOK * NEXP];
__device__ float g_wn[NTOK];
__device__ float g_psum[NTOK * CH];
__device__ float g_psumsq[NTOK * CH];

typedef unsigned long long u64;

// ---- f32x2 helpers (Blackwell packed fp32; ptxas never auto-fuses) ----
__device__ __forceinline__ u64 pack2(float x, float y) {
    u64 r; asm("mov.b64 %0, {%1, %2};" : "=l"(r) : "f"(x), "f"(y)); return r;
}
__device__ __forceinline__ void unpack2(u64 v, float& x, float& y) {
    asm("mov.b64 {%0, %1}, %2;" : "=f"(x), "=f"(y) : "l"(v));
}
__device__ __forceinline__ u64 ffma2(u64 a, u64 b, u64 c) {
    u64 d; asm("fma.rn.f32x2 %0, %1, %2, %3;" : "=l"(d) : "l"(a), "l"(b), "l"(c));
    return d;
}
// returns {hi(a), lo(b)}
__device__ __forceinline__ u64 shiftp(u64 a, u64 b) {
    u64 r;
    asm("{\n\t.reg .f32 al, ah, bl, bh;\n\t"
        "mov.b64 {al, ah}, %1;\n\t"
        "mov.b64 {bl, bh}, %2;\n\t"
        "mov.b64 %0, {ah, bl};\n\t}"
        : "=l"(r) : "l"(a), "l"(b));
    return r;
}

// ============================================================
// K1: stem conv3x3 (3->32) + BN + SiLU -> tokens; fused channel means
// ============================================================
__global__ void __launch_bounds__(256)
k1_stem(const float* __restrict__ X, const float* __restrict__ W,
        const float* __restrict__ bnw, const float* __restrict__ bnb) {
    __shared__ __align__(16) float sIn[3 * 18 * 18];
    __shared__ __align__(16) float sW[32 * 28];   // padded to 28/row for b64 pairs
    __shared__ float sBw[32], sBb[32];
    __shared__ float sPart[8 * 32];
    int n = blockIdx.x;
    int b = n / 196, pr = (n % 196) / HP, pc = n % HP;
    int tid = threadIdx.x;

    for (int i = tid; i < 3 * 18 * 18; i += 256) {
        int ci = i / 324, r = (i % 324) / 18, c = i % 18;
        int gy = pr * 16 + r - 1, gx = pc * 16 + c - 1;
        float v = 0.f;
        if (gy >= 0 && gy < HWD && gx >= 0 && gx < HWD)
            v = X[((b * 3 + ci) * HWD + gy) * HWD + gx];
        sIn[i] = v;
    }
    for (int i = tid; i < 32 * 28; i += 256) {
        int co = i / 28, k = i % 28;
        sW[i] = (k < 27) ? W[co * 27 + k] : 0.f;
    }
    if (tid < 32) { sBw[tid] = bnw[tid]; sBb[tid] = bnb[tid]; }
    __syncthreads();

    int py = tid >> 4, px = tid & 15;
    float xin[28];
#pragma unroll
    for (int ci = 0; ci < 3; ci++)
#pragma unroll
        for (int dy = 0; dy < 3; dy++)
#pragma unroll
            for (int dx = 0; dx < 3; dx++)
                xin[ci * 9 + dy * 3 + dx] = sIn[ci * 324 + (py + dy) * 18 + (px + dx)];
    xin[27] = 0.f;
    u64 xp[14];
#pragma unroll
    for (int j = 0; j < 14; j++) xp[j] = pack2(xin[2 * j], xin[2 * j + 1]);

    int lane = tid & 31, wid = tid >> 5;
    for (int co = 0; co < 32; co++) {
        u64 acc = 0ULL;
#pragma unroll
        for (int j = 0; j < 14; j++)
            acc = ffma2(*(const u64*)(sW + co * 28 + 2 * j), xp[j], acc);
        float a0, a1; unpack2(acc, a0, a1);
        float a = a0 + a1;
        a = a * sBw[co] + sBb[co];
        float s = a / (1.f + __expf(-a));
        g_tokens[(n * CH + co) * NPIX + tid] = s;
        float ws = s;
#pragma unroll
        for (int off = 16; off > 0; off >>= 1)
            ws += __shfl_down_sync(0xffffffffu, ws, off);
        if (lane == 0) sPart[wid * 32 + co] = ws;
    }
    __syncthreads();
    if (tid < 32) {
        float sum = 0.f;
#pragma unroll
        for (int w = 0; w < 8; w++) sum += sPart[w * 32 + tid];
        g_cmean[n * CH + tid] = sum * (1.f / 256.f);
    }
}

// ============================================================
// K2: gate — one thread per token. 13 blocks x 128 threads.
// ============================================================
__global__ void __launch_bounds__(128)
k2_gate(const float* __restrict__ gate_w, const float* __restrict__ gate_b) {
    __shared__ float sGw[50 * 8];
    __shared__ float sGb[8];
    __shared__ float tab[14][9];
    int tid = threadIdx.x;

    for (int i = tid; i < 400; i += 128) sGw[i] = gate_w[i];
    if (tid < 8) sGb[tid] = gate_b[tid];
    if (tid < 56) {
        int b2 = tid >> 2, k = tid & 3;
        float f = (float)(1 << k) * PI_F;
        float ss = 0.f, cs = 0.f;
        for (int r = 0; r < 16; r++) {
            float ang = f * ((16.f * b2 + (float)r + 0.5f) / 224.f);
            ss += sinf(ang); cs += cosf(ang);
        }
        tab[b2][1 + 2 * k] = ss * (1.f / 16.f);
        tab[b2][2 + 2 * k] = cs * (1.f / 16.f);
    } else if (tid < 70) {
        int b2 = tid - 56;
        tab[b2][0] = (16.f * b2 + 8.f) / 224.f;
    }
    __syncthreads();

    int n = blockIdx.x * 128 + tid;
    if (n >= NTOK) return;
    int pr = (n % 196) / HP, pc = n % HP;

    float l[8];
#pragma unroll
    for (int e = 0; e < 8; e++) l[e] = sGb[e];
    const float4* cm4 = (const float4*)&g_cmean[n * CH];
#pragma unroll
    for (int i4 = 0; i4 < 8; i4++) {
        float4 v4 = cm4[i4];
        float vv[4] = {v4.x, v4.y, v4.z, v4.w};
#pragma unroll
        for (int q = 0; q < 4; q++) {
            int i = i4 * 4 + q;
#pragma unroll
            for (int e = 0; e < 8; e++) l[e] = fmaf(vv[q], sGw[i * 8 + e], l[e]);
        }
    }
    {
        float v0 = tab[pr][0], v1 = tab[pc][0];
#pragma unroll
        for (int e = 0; e < 8; e++) {
            l[e] = fmaf(v0, sGw[32 * 8 + e], l[e]);
            l[e] = fmaf(v1, sGw[33 * 8 + e], l[e]);
        }
    }
#pragma unroll
    for (int k = 0; k < 4; k++) {
#pragma unroll
        for (int sub = 0; sub < 4; sub++) {
            float v = (sub < 2) ? tab[pr][1 + 2 * k + sub] : tab[pc][1 + 2 * k + (sub - 2)];
#pragma unroll
            for (int e = 0; e < 8; e++)
                l[e] = fmaf(v, sGw[(34 + 4 * k + sub) * 8 + e], l[e]);
        }
    }
    float mx = l[0]; int am = 0;
#pragma unroll
    for (int e = 1; e < 8; e++) if (l[e] > mx) { mx = l[e]; am = e; }
    float pe[8], se = 0.f;
#pragma unroll
    for (int e = 0; e < 8; e++) { pe[e] = __expf(l[e] - mx); se += pe[e]; }
    float inv = 1.f / se;
#pragma unroll
    for (int e = 0; e < 8; e++) g_probs[n * 8 + e] = pe[e] * inv;
    g_top1[n] = am;
    g_ptop[n] = pe[am] * inv;
    g_lse[n] = mx + __logf(se);
}

// ============================================================
// K3: capacity scan (ballot, exact token order) + loss reductions
// ============================================================
__global__ void __launch_bounds__(512)
k3_dispatch(float* __restrict__ d_out) {
    __shared__ int   sT[NTOK];
    __shared__ float sbuf[512];
    __shared__ float sres[17];
    __shared__ int   sWC[16 * 9];
    __shared__ int   sRun[8];
    int tid = threadIdx.x;

    for (int i = tid; i < NTOK; i += 512) sT[i] = g_top1[i];
    if (tid < 8) sRun[tid] = 0;
    if (tid < 144) sWC[tid] = 0;
    __syncthreads();

    float part[17];
#pragma unroll
    for (int q = 0; q < 17; q++) part[q] = 0.f;
    for (int n = tid; n < NTOK; n += 512) {
        float lse = g_lse[n];
        part[0] += lse * lse;
        const float4* p4 = (const float4*)&g_probs[n * 8];
        float4 a = p4[0], b = p4[1];
        part[1] += a.x; part[2] += a.y; part[3] += a.z; part[4] += a.w;
        part[5] += b.x; part[6] += b.y; part[7] += b.z; part[8] += b.w;
        part[9 + sT[n]] += 1.f;
    }

    // capacity scan: chunked ballot prefix, exact token-index order
    int lane = tid & 31, wid = tid >> 5;
    for (int c = 0; c < 4; c++) {
        int n = c * 512 + tid;
        bool act = n < NTOK;
        int e = act ? sT[n] : 8;
        unsigned m = __match_any_sync(0xffffffffu, e);
        int lr = __popc(m & ((1u << lane) - 1u));
        if (lr == 0) sWC[wid * 9 + e] = __popc(m);
        __syncthreads();
        if (act) {
            int base = sRun[e];
            for (int w2 = 0; w2 < wid; w2++) base += sWC[w2 * 9 + e];
            int rank = base + lr;
            g_wn[n] = (rank < CAPN) ? g_ptop[n] : 0.f;
        }
        int s = 0;
        if (tid < 8) for (int w2 = 0; w2 < 16; w2++) s += sWC[w2 * 9 + tid];
        __syncthreads();
        if (tid < 8) sRun[tid] += s;
        if (tid < 144) sWC[tid] = 0;
        __syncthreads();
    }

    // loss reductions
    for (int q = 0; q < 17; q++) {
        sbuf[tid] = part[q];
        __syncthreads();
        for (int s2 = 256; s2 > 0; s2 >>= 1) {
            if (tid < s2) sbuf[tid] += sbuf[tid + s2];
            __syncthreads();
        }
        if (tid == 0) sres[q] = sbuf[0];
        __syncthreads();
    }
    if (tid == 0) {
        float z = sres[0] / (float)NTOK;
        float imb = 0.f;
        for (int e = 0; e < 8; e++) imb += sres[1 + e] * sres[9 + e];
        imb *= (float)NEXP / ((float)NTOK * (float)NTOK);
        d_out[8000] = z;
        d_out[8001] = imb;
    }
}

// ============================================================
// K4: expert conv3x3 (32->32) + SiLU + combine, f32x2 packed math
// ============================================================
template <int PAR>
__device__ __forceinline__ void ldw9(const float* __restrict__ wp, float* w) {
    if (PAR == 0) {
        float2 a = *(const float2*)(wp);
        float2 b = *(const float2*)(wp + 2);
        float2 c = *(const float2*)(wp + 4);
        float2 d = *(const float2*)(wp + 6);
        w[0] = a.x; w[1] = a.y; w[2] = b.x; w[3] = b.y;
        w[4] = c.x; w[5] = c.y; w[6] = d.x; w[7] = d.y;
        w[8] = wp[8];
    } else {
        w[0] = wp[0];
        float2 a = *(const float2*)(wp + 1);
        float2 b = *(const float2*)(wp + 3);
        float2 c = *(const float2*)(wp + 5);
        float2 d = *(const float2*)(wp + 7);
        w[1] = a.x; w[2] = a.y; w[3] = b.x; w[4] = b.y;
        w[5] = c.x; w[6] = c.y; w[7] = d.x; w[8] = d.y;
    }
}

template <int PAR>
__device__ __forceinline__ void conv_ci(int ci, const float* sXb,
                                        const float* __restrict__ wbase,
                                        u64 acc[4][4]) {
    u64 ev[3][5], od[3][4];
#pragma unroll
    for (int dy = 0; dy < 3; dy++) {
        const float* rp = sXb + ci * 324 + dy * 18;
#pragma unroll
        for (int j = 0; j < 5; j++) ev[dy][j] = *(const u64*)(rp + 2 * j);
#pragma unroll
        for (int j = 0; j < 4; j++) od[dy][j] = shiftp(ev[dy][j], ev[dy][j + 1]);
    }
#pragma unroll
    for (int c4 = 0; c4 < 4; c4++) {
        const float* wp = wbase + (c4 * CH + ci) * 9;
        float w[9];
        ldw9<PAR>(wp, w);
#pragma unroll
        for (int ky = 0; ky < 3; ky++) {
            u64 w0 = pack2(w[ky * 3 + 0], w[ky * 3 + 0]);
            u64 w1 = pack2(w[ky * 3 + 1], w[ky * 3 + 1]);
            u64 w2 = pack2(w[ky * 3 + 2], w[ky * 3 + 2]);
#pragma unroll
            for (int j = 0; j < 4; j++) {
                acc[c4][j] = ffma2(w0, ev[ky][j], acc[c4][j]);
                acc[c4][j] = ffma2(w1, od[ky][j], acc[c4][j]);
                acc[c4][j] = ffma2(w2, ev[ky][j + 1], acc[c4][j]);
            }
        }
    }
}

__global__ void __launch_bounds__(256, 2)
k4_expert(const float* __restrict__ EW, const float* __restrict__ EB,
          const float* __restrict__ gamma) {
    __shared__ __align__(16) float sX[CH * 324];  // zero-padded token (18x18 per ch)
    int n = blockIdx.x;
    int tid = threadIdx.x;
    float wn = g_wn[n];
    int e = g_top1[n];

    for (int i = tid; i < CH * 324 / 2; i += 256) ((u64*)sX)[i] = 0ULL;
    __syncthreads();
    const float4* src = (const float4*)(g_tokens + (size_t)n * CH * NPIX);
    for (int i = tid; i < CH * NPIX / 4; i += 256) {
        float4 v = src[i];
        int c = i >> 6;
        int p = (i & 63) * 4;
        float* dst = sX + c * 324 + ((p >> 4) + 1) * 18 + (p & 15) + 1;
        dst[0] = v.x; dst[1] = v.y; dst[2] = v.z; dst[3] = v.w;
    }
    __syncthreads();

    int wid = tid >> 5, lane = tid & 31;
    int row = lane >> 1, xb = (lane & 1) * 8;

    u64 acc[4][4];
#pragma unroll
    for (int a = 0; a < 4; a++)
#pragma unroll
        for (int j = 0; j < 4; j++) acc[a][j] = 0ULL;

    const float* wbase = EW + ((size_t)e * CH + wid * 4) * CH * 9;
    const float* sXb = sX + row * 18 + xb;

#pragma unroll 1
    for (int ci2 = 0; ci2 < 16; ci2++) {
        conv_ci<0>(2 * ci2, sXb, wbase, acc);
        conv_ci<1>(2 * ci2 + 1, sXb, wbase, acc);
    }

    // epilogue: y = silu(acc + b); v = t + gamma*wn*y; per-channel sum/sumsq
#pragma unroll
    for (int c4 = 0; c4 < 4; c4++) {
        int co = wid * 4 + c4;
        float bco = EB[e * CH + co];
        float gm = gamma[co] * wn;
        float s = 0.f, ss = 0.f;
#pragma unroll
        for (int j = 0; j < 4; j++) {
            float y0, y1; unpack2(acc[c4][j], y0, y1);
            float a0 = y0 + bco; a0 = a0 / (1.f + __expf(-a0));
            float a1 = y1 + bco; a1 = a1 / (1.f + __expf(-a1));
            float t0 = sX[co * 324 + (row + 1) * 18 + (xb + 1 + 2 * j)];
            float t1 = sX[co * 324 + (row + 1) * 18 + (xb + 2 + 2 * j)];
            float v0 = t0 + gm * a0;
            float v1 = t1 + gm * a1;
            s += v0; ss = fmaf(v0, v0, ss);
            s += v1; ss = fmaf(v1, v1, ss);
        }
#pragma unroll
        for (int off = 16; off > 0; off >>= 1) {
            s  += __shfl_down_sync(0xffffffffu, s, off);
            ss += __shfl_down_sync(0xffffffffu, ss, off);
        }
        if (lane == 0) { g_psum[n * CH + co] = s; g_psumsq[n * CH + co] = ss; }
    }
}

// ============================================================
// K5: GroupNorm(from moments) + pool + LayerNorm + head
// ============================================================
__global__ void __launch_bounds__(256)
k5_head(const float* __restrict__ gnw, const float* __restrict__ gnb,
        const float* __restrict__ lnw, const float* __restrict__ lnb,
        const float* __restrict__ hw, const float* __restrict__ hb,
        float* __restrict__ d_out) {
    __shared__ float sS8[8 * 32], sSS8[8 * 32];
    __shared__ float sS[32], sF[32], sFN[32];
    __shared__ float sMg[8], sRg[8];
    int b = blockIdx.x, tid = threadIdx.x;
    {
        int c = tid & 31, sl = tid >> 5;      // 8 token-slices x 32 channels
        float S = 0.f, SS = 0.f;
        for (int t = sl; t < 196; t += 8) {
            int idx = (b * 196 + t) * CH + c;
            S += g_psum[idx]; SS += g_psumsq[idx];
        }
        sS8[sl * 32 + c] = S; sSS8[sl * 32 + c] = SS;
    }
    __syncthreads();
    if (tid < 32) {
        float S = 0.f, SS = 0.f;
#pragma unroll
        for (int sl = 0; sl < 8; sl++) { S += sS8[sl * 32 + tid]; SS += sSS8[sl * 32 + tid]; }
        sS[tid] = S; sS8[tid] = S; sSS8[tid] = SS;   // reuse row 0 as channel totals
    }
    __syncthreads();
    if (tid < 8) {
        float S  = sS8[tid * 4] + sS8[tid * 4 + 1] + sS8[tid * 4 + 2] + sS8[tid * 4 + 3];
        float SS = sSS8[tid * 4] + sSS8[tid * 4 + 1] + sSS8[tid * 4 + 2] + sSS8[tid * 4 + 3];
        const float inv = 1.f / (4.f * 50176.f);
        float m = S * inv;
        float ex2 = SS * inv;
        sMg[tid] = m;
        sRg[tid] = rsqrtf(ex2 - m * m + EPSV);
    }
    __syncthreads();
    if (tid < 32) {
        float mx = sS[tid] * (1.f / 50176.f);
        int g = tid >> 2;
        sF[tid] = (mx - sMg[g]) * sRg[g] * gnw[tid] + gnb[tid];
    }
    __syncthreads();
    if (tid == 0) {
        float mu = 0.f;
        for (int c = 0; c < 32; c++) mu += sF[c];
        mu *= (1.f / 32.f);
        float va = 0.f;
        for (int c = 0; c < 32; c++) { float d = sF[c] - mu; va = fmaf(d, d, va); }
        va *= (1.f / 32.f);
        float r = rsqrtf(va + EPSV);
        for (int c = 0; c < 32; c++) sFN[c] = (sF[c] - mu) * r * lnw[c] + lnb[c];
    }
    __syncthreads();
    for (int j = tid; j < NCLS; j += blockDim.x) {
        float a = hb[j];
#pragma unroll
        for (int c = 0; c < 32; c++) a = fmaf(sFN[c], hw[c * NCLS + j], a);
        d_out[b * NCLS + j] = a;
    }
}

// ============================================================
extern "C" void kernel_launch(void* const* d_in, const int* in_sizes, int n_in,
                              void* d_out, int out_size) {
    const float* X        = (const float*)d_in[0];
    const float* stem_w   = (const float*)d_in[1];
    const float* bn_w     = (const float*)d_in[2];
    const float* bn_b     = (const float*)d_in[3];
    const float* gate_w   = (const float*)d_in[4];
    const float* gate_b   = (const float*)d_in[5];
    const float* expert_w = (const float*)d_in[6];
    const float* expert_b = (const float*)d_in[7];
    const float* gamma    = (const float*)d_in[8];
    const float* gn_w     = (const float*)d_in[9];
    const float* gn_b     = (const float*)d_in[10];
    const float* ln_w     = (const float*)d_in[11];
    const float* ln_b     = (const float*)d_in[12];
    const float* head_w   = (const float*)d_in[13];
    const float* head_b   = (const float*)d_in[14];
    float* out = (float*)d_out;

    k1_stem<<<NTOK, 256>>>(X, stem_w, bn_w, bn_b);
    k2_gate<<<(NTOK + 127) / 128, 128>>>(gate_w, gate_b);
    k3_dispatch<<<1, 512>>>(out);
    k4_expert<<<NTOK, 256>>>(expert_w, expert_b, gamma);
    k5_head<<<8, 256>>>(gn_w, gn_b, ln_w, ln_b, head_w, head_b, out);
}